// round 16
// baseline (speedup 1.0000x reference)
#include <cuda_runtime.h>
#include <cuda_fp16.h>
#include <cstdint>
#include <math.h>

// ---------------- problem constants ----------------
constexpr int B_ = 16, N_ = 3136, C_ = 512, H_ = 8, D_ = 64;
constexpr int HH = 56, POOL = 12, AG = 144;
constexpr long M_ = (long)B_ * N_;                 // 50176
constexpr long QKV_ELEMS = M_ * 3 * C_;            // 77,070,336
constexpr long S_ELEMS = (long)B_ * H_ * AG * N_;  // scratch: xh / stage1 partials / yh
constexpr long AV_ELEMS = (long)B_ * H_ * AG * D_; // 1,179,648
constexpr long Y_ELEMS = M_ * C_;                  // 25,690,112

// stage-1 partial buffer offsets (in floats, inside g_S)
constexpr long PART_M = (long)128 * 7 * 144 * 64;  // 8,257,536
constexpr long PART_S = PART_M + 128L * 7 * 144;   // + 129,024

// ---------------- scratch (static device globals; no allocations) ----------------
__device__ __half g_qkvh[QKV_ELEMS];               // qkv as half
__device__ __half g_agenth[(long)B_ * AG * C_];    // agent tokens as half
__device__ float  g_S[S_ELEMS];   // phase A: x half; phase B: stage1 partials; phase C: y half
__device__ float  g_av[AV_ELEMS];
__device__ __half g_wh[1048576];  // half weights: qkv_w @0, proj_w @786432

// ================= small helpers =================
__device__ __forceinline__ uint32_t smem_u32(const void* p) {
    uint32_t a;
    asm("{ .reg .u64 t; cvta.to.shared.u64 t, %1; cvt.u32.u64 %0, t; }" : "=r"(a) : "l"(p));
    return a;
}
__device__ __forceinline__ void cpa16(uint32_t dst, const void* src) {
    asm volatile("cp.async.cg.shared.global [%0], [%1], 16;" :: "r"(dst), "l"(src));
}
#define CP_COMMIT() asm volatile("cp.async.commit_group;" ::: "memory")
template<int N> __device__ __forceinline__ void cp_wait() {
    asm volatile("cp.async.wait_group %0;" :: "n"(N) : "memory");
}
__device__ __forceinline__ void ldsm_x4(uint32_t& r0, uint32_t& r1, uint32_t& r2, uint32_t& r3,
                                        uint32_t addr) {
    asm volatile("ldmatrix.sync.aligned.m8n8.x4.shared.b16 {%0,%1,%2,%3}, [%4];"
        : "=r"(r0), "=r"(r1), "=r"(r2), "=r"(r3) : "r"(addr));
}
__device__ __forceinline__ void mma_tf32(float* c, const uint32_t* a, const uint32_t* b) {
    asm volatile(
        "mma.sync.aligned.m16n8k8.row.col.f32.tf32.tf32.f32 "
        "{%0,%1,%2,%3}, {%4,%5,%6,%7}, {%8,%9}, {%0,%1,%2,%3};"
        : "+f"(c[0]), "+f"(c[1]), "+f"(c[2]), "+f"(c[3])
        : "r"(a[0]), "r"(a[1]), "r"(a[2]), "r"(a[3]), "r"(b[0]), "r"(b[1]));
}
__device__ __forceinline__ void mma_f16(float* c, const uint32_t* a, const uint32_t* b) {
    asm volatile(
        "mma.sync.aligned.m16n8k16.row.col.f32.f16.f16.f32 "
        "{%0,%1,%2,%3}, {%4,%5,%6,%7}, {%8,%9}, {%0,%1,%2,%3};"
        : "+f"(c[0]), "+f"(c[1]), "+f"(c[2]), "+f"(c[3])
        : "r"(a[0]), "r"(a[1]), "r"(a[2]), "r"(a[3]), "r"(b[0]), "r"(b[1]));
}

// ---------------- f32 -> f16 convert pass ----------------
__global__ void f32_to_f16(const float* __restrict__ in, __half* __restrict__ out, long n4)
{
    long i = (long)blockIdx.x * blockDim.x + threadIdx.x;
    if (i >= n4) return;
    float4 v = ((const float4*)in)[i];
    __half2* o = (__half2*)out + 2 * i;
    o[0] = __floats2half2_rn(v.x, v.y);
    o[1] = __floats2half2_rn(v.z, v.w);
}

// ================= large tensor-core GEMM, fp16 in / fp32 accum, f32-or-f16 out =================
// K-chunk = 64; 3-stage cp.async pipeline; ONE __syncthreads per chunk.
constexpr int HPAD = 72;                          // halfs per smem row (144B stride, conflict-free)
constexpr int HSTG = 128 * HPAD;                  // halfs per operand-stage (9216)
constexpr int NSTAGE = 3;
constexpr int GEMM_SMEM_H = NSTAGE * 2 * HSTG * 2; // 110,592 bytes

template<bool OUTH>
__global__ __launch_bounds__(256, 2)
void gemm_mma_h(const __half* __restrict__ A, const __half* __restrict__ Bw,
                void* __restrict__ Cv,
                int K, int lda, int ldb, int ldc, const float* __restrict__ bias)
{
    extern __shared__ __half hsm[];
    const int tid = threadIdx.x;
    const int wid = tid >> 5, lane = tid & 31;
    const int wm = wid >> 2, wn = wid & 3;
    const long m0 = (long)blockIdx.y * 128;
    const long n0 = (long)blockIdx.x * 128;

    const uint32_t sbase = smem_u32(hsm);
    const int g = lane >> 2, t4 = lane & 3;

    // ldmatrix lane address offsets
    const int aRow = lane & 15, aCol = (lane >> 4) << 3;               // A x4
    const int quad = lane >> 3, l8 = lane & 7;
    const int bRow = ((quad >> 1) << 3) + l8, bCol = (quad & 1) << 3;  // B dual-x4
    const uint32_t aFbase = sbase + (uint32_t)(((wm * 64 + aRow) * HPAD + aCol) * 2);
    const uint32_t bFbase = sbase + (uint32_t)((HSTG + (wn * 32 + bRow) * HPAD + bCol) * 2);

    float acc[4][4][4];
#pragma unroll
    for (int i = 0; i < 4; i++)
#pragma unroll
        for (int j = 0; j < 4; j++)
#pragma unroll
            for (int l = 0; l < 4; l++) acc[i][j][l] = 0.f;

    const int nch = K / 64;

    auto issue = [&](int s, int c) {
        const uint32_t so = (uint32_t)(s * 2 * HSTG * 2);
        const long ko = (long)c * 64;
#pragma unroll
        for (int i = 0; i < 4; i++) {
            const int idx = tid + i * 256;       // 0..1023
            const int row = idx >> 3;
            const int sg = (idx & 7) << 3;       // half offset within 64-half row
            const uint32_t soff = so + (uint32_t)((row * HPAD + sg) * 2);
            cpa16(sbase + soff, A + (m0 + row) * (long)lda + ko + sg);
            cpa16(sbase + (uint32_t)(HSTG * 2) + soff, Bw + (n0 + row) * (long)ldb + ko + sg);
        }
        CP_COMMIT();
    };

    issue(0, 0);
    if (nch > 1) issue(1, 1); else CP_COMMIT();

    for (int c = 0; c < nch; c++) {
        cp_wait<1>();          // chunk c's group complete (<=1 younger pending)
        __syncthreads();       // all warps done computing chunk c-1 -> its buffer is free
        if (c + 2 < nch) issue((c + 2) % NSTAGE, c + 2);
        else CP_COMMIT();      // empty group keeps wait-count invariant

        const int s = c % NSTAGE;
        const uint32_t so = (uint32_t)(s * 2 * HSTG * 2);
#pragma unroll
        for (int ks = 0; ks < 4; ks++) {
            uint32_t a[4][4], b[4][2];
#pragma unroll
            for (int mt = 0; mt < 4; mt++)
                ldsm_x4(a[mt][0], a[mt][1], a[mt][2], a[mt][3],
                        aFbase + so + (uint32_t)(((mt * 16) * HPAD + ks * 16) * 2));
#pragma unroll
            for (int j = 0; j < 2; j++)
                ldsm_x4(b[2 * j][0], b[2 * j][1], b[2 * j + 1][0], b[2 * j + 1][1],
                        bFbase + so + (uint32_t)(((j * 16) * HPAD + ks * 16) * 2));
#pragma unroll
            for (int mt = 0; mt < 4; mt++)
#pragma unroll
                for (int nt = 0; nt < 4; nt++)
                    mma_f16(acc[mt][nt], a[mt], b[nt]);
        }
    }

    const long rowBase = m0 + wm * 64 + g;
#pragma unroll
    for (int mt = 0; mt < 4; mt++) {
        const long r0 = rowBase + mt * 16;
#pragma unroll
        for (int nt = 0; nt < 4; nt++) {
            const long col = n0 + wn * 32 + nt * 8 + t4 * 2;
            float2 v0 = make_float2(acc[mt][nt][0], acc[mt][nt][1]);
            float2 v1 = make_float2(acc[mt][nt][2], acc[mt][nt][3]);
            if (bias) {
                float2 bb = *(const float2*)&bias[col];
                v0.x += bb.x; v0.y += bb.y;
                v1.x += bb.x; v1.y += bb.y;
            }
            if (OUTH) {
                __half* C = (__half*)Cv;
                *(__half2*)&C[r0 * (long)ldc + col] = __floats2half2_rn(v0.x, v0.y);
                *(__half2*)&C[(r0 + 8) * (long)ldc + col] = __floats2half2_rn(v1.x, v1.y);
            } else {
                float* C = (float*)Cv;
                *(float2*)&C[r0 * (long)ldc + col] = v0;
                *(float2*)&C[(r0 + 8) * (long)ldc + col] = v1;
            }
        }
    }
}

// ================= fused stage-1 (flash): f16 logits + tf32 P@V =================
constexpr int S1_AGP = 72, S1_KP = 72, S1_VP = 72, S1_PP = 72;
constexpr int S1_KT_OFFH = 144 * S1_AGP;
constexpr int S1_VS_OFFH = S1_KT_OFFH + 64 * S1_KP;
constexpr int S1_VS_B = S1_VS_OFFH * 2;
constexpr int S1_PS_B = S1_VS_B + 64 * S1_VP * 4;
constexpr int S1_SMEM = S1_PS_B + 144 * S1_PP * 4;        // 89,856 bytes

__global__ __launch_bounds__(288)
void stage1_fused(const __half* __restrict__ qkv, const __half* __restrict__ agent,
                  float* __restrict__ part, float scale)
{
    extern __shared__ char s1sm[];
    __half* AgS = (__half*)s1sm;
    __half* Kt  = (__half*)s1sm + S1_KT_OFFH;
    float*  Vs  = (float*)(s1sm + S1_VS_B);
    float*  Ps  = (float*)(s1sm + S1_PS_B);

    const int z = blockIdx.y, split = blockIdx.x;
    const int b = z >> 3, h = z & 7;
    const int tid = threadIdx.x, wid = tid >> 5, lane = tid & 31;
    const int g = lane >> 2, t4 = lane & 3;

    const __half* Agz = agent + (long)b * AG * C_ + h * 64;
    const __half* Kz  = qkv + (long)b * N_ * 1536 + 512 + h * 64;
    const __half* Vz  = qkv + (long)b * N_ * 1536 + 1024 + h * 64;

    for (int i = tid; i < 144 * 8; i += 288) {
        int row = i >> 3, seg = (i & 7) << 3;
        *(uint4*)&AgS[row * S1_AGP + seg] = *(const uint4*)(Agz + (long)row * C_ + seg);
    }
    __syncthreads();

    const int r = wid * 16 + g;

    uint32_t afr[4][4];
#pragma unroll
    for (int ks = 0; ks < 4; ks++) {
        const __half* p = &AgS[r * S1_AGP + ks * 16 + 2 * t4];
        afr[ks][0] = *(const uint32_t*)(p);
        afr[ks][1] = *(const uint32_t*)(p + 8 * S1_AGP);
        afr[ks][2] = *(const uint32_t*)(p + 8);
        afr[ks][3] = *(const uint32_t*)(p + 8 * S1_AGP + 8);
    }

    float m0r = -3.4e38f, m1r = -3.4e38f, s0 = 0.f, s1 = 0.f;
    float O[8][4];
#pragma unroll
    for (int nt = 0; nt < 8; nt++)
#pragma unroll
        for (int l = 0; l < 4; l++) O[nt][l] = 0.f;

    int k0 = split * 448;
    for (int t = 0; t < 7; t++, k0 += 64) {
        __syncthreads();
        for (int i = tid; i < 64 * 8; i += 288) {
            int row = i >> 3, seg = (i & 7) << 3;
            *(uint4*)&Kt[row * S1_KP + seg] = *(const uint4*)(Kz + (long)(k0 + row) * 1536 + seg);
            uint4 vh = *(const uint4*)(Vz + (long)(k0 + row) * 1536 + seg);
            const __half2* hp = (const __half2*)&vh;
            float* vd = &Vs[row * S1_VP + seg];
            float2 f0 = __half22float2(hp[0]), f1 = __half22float2(hp[1]);
            float2 f2 = __half22float2(hp[2]), f3 = __half22float2(hp[3]);
            *(float4*)(vd)     = make_float4(f0.x, f0.y, f1.x, f1.y);
            *(float4*)(vd + 4) = make_float4(f2.x, f2.y, f3.x, f3.y);
        }
        __syncthreads();

        float L[8][4];
#pragma unroll
        for (int nt = 0; nt < 8; nt++)
#pragma unroll
            for (int l = 0; l < 4; l++) L[nt][l] = 0.f;
#pragma unroll
        for (int ks = 0; ks < 4; ks++) {
#pragma unroll
            for (int nt = 0; nt < 8; nt++) {
                uint32_t bb[2];
                const __half* p = &Kt[(nt * 8 + g) * S1_KP + ks * 16 + 2 * t4];
                bb[0] = *(const uint32_t*)(p);
                bb[1] = *(const uint32_t*)(p + 8);
                mma_f16(L[nt], afr[ks], bb);
            }
        }

        float lm0 = -3.4e38f, lm1 = -3.4e38f;
#pragma unroll
        for (int nt = 0; nt < 8; nt++) {
            lm0 = fmaxf(lm0, fmaxf(L[nt][0], L[nt][1]));
            lm1 = fmaxf(lm1, fmaxf(L[nt][2], L[nt][3]));
        }
        lm0 *= scale; lm1 *= scale;
#pragma unroll
        for (int o = 1; o < 4; o <<= 1) {
            lm0 = fmaxf(lm0, __shfl_xor_sync(0xffffffffu, lm0, o));
            lm1 = fmaxf(lm1, __shfl_xor_sync(0xffffffffu, lm1, o));
        }
        float nm0 = fmaxf(m0r, lm0), nm1 = fmaxf(m1r, lm1);
        float al0 = __expf(m0r - nm0), al1 = __expf(m1r - nm1);
        s0 *= al0; s1 *= al1;
#pragma unroll
        for (int nt = 0; nt < 8; nt++) {
            O[nt][0] *= al0; O[nt][1] *= al0; O[nt][2] *= al1; O[nt][3] *= al1;
            float p0 = __expf(L[nt][0] * scale - nm0); s0 += p0;
            float p1 = __expf(L[nt][1] * scale - nm0); s0 += p1;
            float p2 = __expf(L[nt][2] * scale - nm1); s1 += p2;
            float p3 = __expf(L[nt][3] * scale - nm1); s1 += p3;
            int col = nt * 8 + 2 * t4;
            Ps[r * S1_PP + col]           = p0;
            Ps[r * S1_PP + col + 1]       = p1;
            Ps[(r + 8) * S1_PP + col]     = p2;
            Ps[(r + 8) * S1_PP + col + 1] = p3;
        }
        m0r = nm0; m1r = nm1;

#pragma unroll
        for (int ks = 0; ks < 8; ks++) {
            uint32_t a2[4];
            const float* p = &Ps[r * S1_PP + ks * 8 + t4];
            a2[0] = __float_as_uint(p[0]);
            a2[1] = __float_as_uint(p[8 * S1_PP]);
            a2[2] = __float_as_uint(p[4]);
            a2[3] = __float_as_uint(p[8 * S1_PP + 4]);
#pragma unroll
            for (int nt = 0; nt < 8; nt++) {
                uint32_t bb[2];
                bb[0] = __float_as_uint(Vs[(ks * 8 + t4) * S1_VP + nt * 8 + g]);
                bb[1] = __float_as_uint(Vs[(ks * 8 + t4 + 4) * S1_VP + nt * 8 + g]);
                mma_tf32(O[nt], a2, bb);
            }
        }
    }

#pragma unroll
    for (int o = 1; o < 4; o <<= 1) {
        s0 += __shfl_xor_sync(0xffffffffu, s0, o);
        s1 += __shfl_xor_sync(0xffffffffu, s1, o);
    }

    const long pb = ((long)z * 7 + split) * 144;
#pragma unroll
    for (int nt = 0; nt < 8; nt++) {
        int col = nt * 8 + 2 * t4;
        *(float2*)&part[(pb + r) * 64 + col]     = make_float2(O[nt][0], O[nt][1]);
        *(float2*)&part[(pb + r + 8) * 64 + col] = make_float2(O[nt][2], O[nt][3]);
    }
    if (t4 == 0) {
        part[PART_M + pb + r]     = m0r;  part[PART_S + pb + r]     = s0;
        part[PART_M + pb + r + 8] = m1r;  part[PART_S + pb + r + 8] = s1;
    }
}

// merge 7 split partials -> agent_v (float)
__global__ void stage1_merge(const float* __restrict__ part, float* __restrict__ av)
{
    long i = (long)blockIdx.x * 256 + threadIdx.x;
    if (i >= (long)128 * 144 * 16) return;
    int d4 = (int)(i & 15);
    long t = i >> 4;
    int p = (int)(t % 144);
    int z = (int)(t / 144);
    long base = (long)z * 7 * 144 + p;

    float M = -3.4e38f;
#pragma unroll
    for (int sp = 0; sp < 7; sp++)
        M = fmaxf(M, part[PART_M + base + sp * 144]);
    float den = 0.f;
    float4 acc = make_float4(0.f, 0.f, 0.f, 0.f);
#pragma unroll
    for (int sp = 0; sp < 7; sp++) {
        float w = __expf(part[PART_M + base + sp * 144] - M);
        den += w * part[PART_S + base + sp * 144];
        float4 o = *(const float4*)&part[(base + sp * 144) * 64 + d4 * 4];
        acc.x += w * o.x; acc.y += w * o.y; acc.z += w * o.z; acc.w += w * o.w;
    }
    float inv = 1.f / den;
    acc.x *= inv; acc.y *= inv; acc.z *= inv; acc.w *= inv;
    *(float4*)&av[((long)z * 144 + p) * 64 + d4 * 4] = acc;
}

// ================= fused stage-2 (f16 logits) + tf32 P@Av + depthwise conv =================
constexpr int S2_AP = 72, S2_BP = 72, S2_PP = 148, S2_VP = 72;
constexpr int S2_VS_OFF = 128 * S2_PP;
constexpr int S2_W_OFF  = S2_VS_OFF + AG * S2_VP;
constexpr int S2_SMEM = (S2_W_OFF + 576 + 64) * 4;        // 119,808 bytes

__global__ __launch_bounds__(256)
void stage2_fused(const __half* __restrict__ Q, const __half* __restrict__ Ag,
                  const float* __restrict__ Av, __half* __restrict__ Y,
                  const float* __restrict__ dwcW, const float* __restrict__ dwcB,
                  float scale)
{
    extern __shared__ float sm[];
    __half* As = (__half*)sm;
    __half* Bs = (__half*)sm + 128 * S2_AP;
    float*  Ps = sm;
    float*  Vs = sm + S2_VS_OFF;
    float*  Ws = sm + S2_W_OFF;
    float*  Bb = sm + S2_W_OFF + 576;

    const int z = blockIdx.y;
    const int b = z >> 3, h = z & 7;
    const __half* Qz  = Q + (long)b * N_ * 1536 + h * 64;
    const __half* Agz = Ag + (long)b * AG * C_ + h * 64;
    const float*  Avz = Av + (long)z * AG * 64;
    const __half* vb  = Q + (long)b * N_ * 1536 + 1024 + h * 64;
    __half* Yz = Y + (long)b * N_ * C_ + h * 64;

    const int tid = threadIdx.x;
    const int wid = tid >> 5, lane = tid & 31;
    const int g = lane >> 2, t4 = lane & 3;
    const int m0 = blockIdx.x * 128;

#pragma unroll
    for (int i = 0; i < 4; i++) {
        int idx = tid + i * 256;
        int row = idx >> 3, seg = (idx & 7) << 3;
        uint4 v = make_uint4(0u, 0u, 0u, 0u);
        if (m0 + row < N_)
            v = *(const uint4*)(Qz + (long)(m0 + row) * 1536 + seg);
        *(uint4*)&As[row * S2_AP + seg] = v;
    }
    for (int i = tid; i < 144 * 8; i += 256) {
        int row = i >> 3, seg = (i & 7) << 3;
        *(uint4*)&Bs[row * S2_BP + seg] = *(const uint4*)(Agz + (long)row * C_ + seg);
    }
#pragma unroll
    for (int i = 0; i < 9; i++) {
        int idx = tid + i * 256;
        int row = idx >> 4, c4 = (idx & 15) << 2;
        *(float4*)&Vs[row * S2_VP + c4] = *(const float4*)(Avz + (long)row * 64 + c4);
    }
    for (int i = tid; i < 640; i += 256) {
        if (i < 576) Ws[i] = dwcW[h * 576 + i];
        else         Bb[i - 576] = dwcB[h * 64 + i - 576];
    }
    __syncthreads();

    const int r = wid * 16 + g;
    float accL[18][4];
#pragma unroll
    for (int nt = 0; nt < 18; nt++)
#pragma unroll
        for (int l = 0; l < 4; l++) accL[nt][l] = 0.f;

#pragma unroll
    for (int ks = 0; ks < 4; ks++) {
        uint32_t a[4];
        {
            const __half* p = &As[r * S2_AP + ks * 16 + 2 * t4];
            a[0] = *(const uint32_t*)(p);
            a[1] = *(const uint32_t*)(p + 8 * S2_AP);
            a[2] = *(const uint32_t*)(p + 8);
            a[3] = *(const uint32_t*)(p + 8 * S2_AP + 8);
        }
#pragma unroll
        for (int nt = 0; nt < 18; nt++) {
            uint32_t bfr[2];
            const __half* p = &Bs[(nt * 8 + g) * S2_BP + ks * 16 + 2 * t4];
            bfr[0] = *(const uint32_t*)(p);
            bfr[1] = *(const uint32_t*)(p + 8);
            mma_f16(accL[nt], a, bfr);
        }
    }

    float m0r = -3.4e38f, m1r = -3.4e38f;
#pragma unroll
    for (int nt = 0; nt < 18; nt++) {
        m0r = fmaxf(m0r, fmaxf(accL[nt][0], accL[nt][1]));
        m1r = fmaxf(m1r, fmaxf(accL[nt][2], accL[nt][3]));
    }
    m0r *= scale; m1r *= scale;
#pragma unroll
    for (int o = 1; o < 4; o <<= 1) {
        m0r = fmaxf(m0r, __shfl_xor_sync(0xffffffffu, m0r, o));
        m1r = fmaxf(m1r, __shfl_xor_sync(0xffffffffu, m1r, o));
    }
    float s0 = 0.f, s1 = 0.f;
#pragma unroll
    for (int nt = 0; nt < 18; nt++) {
        accL[nt][0] = __expf(accL[nt][0] * scale - m0r); s0 += accL[nt][0];
        accL[nt][1] = __expf(accL[nt][1] * scale - m0r); s0 += accL[nt][1];
        accL[nt][2] = __expf(accL[nt][2] * scale - m1r); s1 += accL[nt][2];
        accL[nt][3] = __expf(accL[nt][3] * scale - m1r); s1 += accL[nt][3];
    }
#pragma unroll
    for (int o = 1; o < 4; o <<= 1) {
        s0 += __shfl_xor_sync(0xffffffffu, s0, o);
        s1 += __shfl_xor_sync(0xffffffffu, s1, o);
    }
    const float inv0 = 1.0f / s0, inv1 = 1.0f / s1;

    __syncthreads();

#pragma unroll
    for (int nt = 0; nt < 18; nt++) {
        const int col = nt * 8 + 2 * t4;
        Ps[r * S2_PP + col]           = accL[nt][0] * inv0;
        Ps[r * S2_PP + col + 1]       = accL[nt][1] * inv0;
        Ps[(r + 8) * S2_PP + col]     = accL[nt][2] * inv1;
        Ps[(r + 8) * S2_PP + col + 1] = accL[nt][3] * inv1;
    }
    __syncthreads();

    float acc2[8][4];
#pragma unroll
    for (int nt = 0; nt < 8; nt++)
#pragma unroll
        for (int l = 0; l < 4; l++) acc2[nt][l] = 0.f;

#pragma unroll
    for (int ks = 0; ks < 18; ks++) {
        uint32_t a[4];
        {
            const float* p = &Ps[r * S2_PP + ks * 8 + t4];
            a[0] = __float_as_uint(p[0]);
            a[1] = __float_as_uint(p[8 * S2_PP]);
            a[2] = __float_as_uint(p[4]);
            a[3] = __float_as_uint(p[8 * S2_PP + 4]);
        }
#pragma unroll
        for (int nt = 0; nt < 8; nt++) {
            uint32_t bfr[2];
            bfr[0] = __float_as_uint(Vs[(ks * 8 + t4) * S2_VP + nt * 8 + g]);
            bfr[1] = __float_as_uint(Vs[(ks * 8 + t4 + 4) * S2_VP + nt * 8 + g]);
            mma_tf32(acc2[nt], a, bfr);
        }
    }

    const int gr = m0 + r;
#pragma unroll
    for (int rr = 0; rr < 2; rr++) {
        const int l = gr + rr * 8;
        if (l >= N_) continue;
        const int hh = l / 56, ww = l - hh * 56;
        float add[16];
#pragma unroll
        for (int nt = 0; nt < 8; nt++) {
            int c0 = nt * 8 + 2 * t4;
            add[nt * 2]     = Bb[c0];
            add[nt * 2 + 1] = Bb[c0 + 1];
        }
#pragma unroll
        for (int kh = 0; kh < 3; kh++) {
            int h2 = hh + kh - 1;
            if (h2 < 0 || h2 >= 56) continue;
#pragma unroll
            for (int kw = 0; kw < 3; kw++) {
                int w2 = ww + kw - 1;
                if (w2 < 0 || w2 >= 56) continue;
                const __half* vrow = vb + (long)(h2 * 56 + w2) * 1536;
                const int j = kh * 3 + kw;
#pragma unroll
                for (int nt = 0; nt < 8; nt++) {
                    int c0 = nt * 8 + 2 * t4;
                    float2 vv = __half22float2(*(const __half2*)&vrow[c0]);
                    add[nt * 2]     = fmaf(vv.x, Ws[c0 * 9 + j],       add[nt * 2]);
                    add[nt * 2 + 1] = fmaf(vv.y, Ws[(c0 + 1) * 9 + j], add[nt * 2 + 1]);
                }
            }
        }
#pragma unroll
        for (int nt = 0; nt < 8; nt++) {
            const int col = nt * 8 + 2 * t4;
            __half2 hv = __floats2half2_rn(acc2[nt][rr * 2]     + add[nt * 2],
                                           acc2[nt][rr * 2 + 1] + add[nt * 2 + 1]);
            *(__half2*)&Yz[(long)l * C_ + col] = hv;
        }
    }
}

// ---------------- adaptive avg pool of q (half) -> agent tokens (half) ----------------
__global__ void pool_kernel(const __half* __restrict__ qkv, __half* __restrict__ agent)
{
    int b = blockIdx.x;
    int pq = blockIdx.y;
    int p = pq / POOL, q = pq % POOL;
    int ch = threadIdx.x;
    int hs = (p * HH) / POOL, he = ((p + 1) * HH + POOL - 1) / POOL;
    int ws = (q * HH) / POOL, we = ((q + 1) * HH + POOL - 1) / POOL;
    float inv = 1.0f / (float)((he - hs) * (we - ws));
    const __half* base = qkv + (long)b * N_ * 1536;
    float s = 0.f;
    for (int h = hs; h < he; h++)
        for (int w = ws; w < we; w++)
            s += __half2float(base[(long)(h * HH + w) * 1536 + ch]);
    agent[((long)b * AG + pq) * C_ + ch] = __float2half(s * inv);
}

// ---------------- launch ----------------
extern "C" void kernel_launch(void* const* d_in, const int* in_sizes, int n_in,
                              void* d_out, int out_size)
{
    const float* x      = (const float*)d_in[0];
    const float* qkv_w  = (const float*)d_in[1];
    const float* proj_w = (const float*)d_in[2];
    const float* proj_b = (const float*)d_in[3];
    const float* dwc_w  = (const float*)d_in[4];
    const float* dwc_b  = (const float*)d_in[5];
    float* out = (float*)d_out;

    __half *qkvh, *agenth, *wh;
    float *S, *av;
    cudaGetSymbolAddress((void**)&qkvh,   g_qkvh);
    cudaGetSymbolAddress((void**)&agenth, g_agenth);
    cudaGetSymbolAddress((void**)&S,      g_S);
    cudaGetSymbolAddress((void**)&av,     g_av);
    cudaGetSymbolAddress((void**)&wh,     g_wh);
    __half* xh = (__half*)S;
    __half* yh = (__half*)S;

    cudaFuncSetAttribute(gemm_mma_h<true>,  cudaFuncAttributeMaxDynamicSharedMemorySize, GEMM_SMEM_H);
    cudaFuncSetAttribute(gemm_mma_h<false>, cudaFuncAttributeMaxDynamicSharedMemorySize, GEMM_SMEM_H);
    cudaFuncSetAttribute(stage1_fused, cudaFuncAttributeMaxDynamicSharedMemorySize, S1_SMEM);
    cudaFuncSetAttribute(stage2_fused, cudaFuncAttributeMaxDynamicSharedMemorySize, S2_SMEM);

    const float scale = 0.125f;

    // 0) convert x, qkv_w, proj_w to fp16 (proj_w stored at wh+786432)
    {
        long n4 = Y_ELEMS / 4;
        f32_to_f16<<<(int)((n4 + 255) / 256), 256>>>(x, xh, n4);
        long w4 = 786432 / 4;
        f32_to_f16<<<(int)((w4 + 255) / 256), 256>>>(qkv_w, wh, w4);
        long p4 = 262144 / 4;
        f32_to_f16<<<(int)((p4 + 255) / 256), 256>>>(proj_w, wh + 786432, p4);
    }

    // 1) qkv(half) = x @ qkv_w^T
    gemm_mma_h<true><<<dim3(12, 392), 256, GEMM_SMEM_H>>>(xh, wh, qkvh, 512, 512, 512, 1536, nullptr);

    // 2) agent tokens (half)
    pool_kernel<<<dim3(B_, AG), 512>>>(qkvh, agenth);

    // 3+4+5) fused flash stage-1 -> partials (g_S; xh dead) -> merge into agent_v
    stage1_fused<<<dim3(7, 128), 288, S1_SMEM>>>(qkvh, agenth, S, scale);
    stage1_merge<<<1152, 256>>>(S, av);

    // 6+7+8+9) fused: y(half) = softmax(scale*qh@agent^T) @ agent_v + dwc(v) + dwc_b
    stage2_fused<<<dim3(25, 128), 256, S2_SMEM>>>(qkvh, agenth, av, yh, dwc_w, dwc_b, scale);

    // 10) out = y @ proj_w^T + proj_b
    gemm_mma_h<false><<<dim3(4, 392), 256, GEMM_SMEM_H>>>(yh, wh + 786432, out, 512, 512, 512, 512, proj_b);
}

// round 17
// speedup vs baseline: 1.1217x; 1.1217x over previous
#include <cuda_runtime.h>
#include <cuda_fp16.h>
#include <cstdint>
#include <math.h>

// ---------------- problem constants ----------------
constexpr int B_ = 16, N_ = 3136, C_ = 512, H_ = 8, D_ = 64;
constexpr int HH = 56, POOL = 12, AG = 144;
constexpr long M_ = (long)B_ * N_;                 // 50176
constexpr long QKV_ELEMS = M_ * 3 * C_;            // 77,070,336
constexpr long S_ELEMS = (long)B_ * H_ * AG * N_;  // scratch: xh / stage1 partials / yh
constexpr long AV_ELEMS = (long)B_ * H_ * AG * D_; // 1,179,648
constexpr long Y_ELEMS = M_ * C_;                  // 25,690,112

// stage-1 partial buffer offsets (in floats, inside g_S)
constexpr long PART_M = (long)128 * 7 * 144 * 64;  // 8,257,536
constexpr long PART_S = PART_M + 128L * 7 * 144;   // + 129,024

// ---------------- scratch (static device globals; no allocations) ----------------
__device__ __half g_qkvh[QKV_ELEMS];               // qkv as half
__device__ __half g_agenth[(long)B_ * AG * C_];    // agent tokens as half
__device__ float  g_S[S_ELEMS];   // phase A: x half; phase B: stage1 partials; phase C: y half
__device__ __half g_avh[AV_ELEMS];                 // agent_v as half
__device__ __half g_wh[1048576];  // half weights: qkv_w @0, proj_w @786432

// ================= small helpers =================
__device__ __forceinline__ uint32_t smem_u32(const void* p) {
    uint32_t a;
    asm("{ .reg .u64 t; cvta.to.shared.u64 t, %1; cvt.u32.u64 %0, t; }" : "=r"(a) : "l"(p));
    return a;
}
__device__ __forceinline__ void cpa16(uint32_t dst, const void* src) {
    asm volatile("cp.async.cg.shared.global [%0], [%1], 16;" :: "r"(dst), "l"(src));
}
#define CP_COMMIT() asm volatile("cp.async.commit_group;" ::: "memory")
template<int N> __device__ __forceinline__ void cp_wait() {
    asm volatile("cp.async.wait_group %0;" :: "n"(N) : "memory");
}
__device__ __forceinline__ void ldsm_x4(uint32_t& r0, uint32_t& r1, uint32_t& r2, uint32_t& r3,
                                        uint32_t addr) {
    asm volatile("ldmatrix.sync.aligned.m8n8.x4.shared.b16 {%0,%1,%2,%3}, [%4];"
        : "=r"(r0), "=r"(r1), "=r"(r2), "=r"(r3) : "r"(addr));
}
__device__ __forceinline__ void ldsm_x4_t(uint32_t& r0, uint32_t& r1, uint32_t& r2, uint32_t& r3,
                                          uint32_t addr) {
    asm volatile("ldmatrix.sync.aligned.m8n8.x4.trans.shared.b16 {%0,%1,%2,%3}, [%4];"
        : "=r"(r0), "=r"(r1), "=r"(r2), "=r"(r3) : "r"(addr));
}
__device__ __forceinline__ void mma_f16(float* c, const uint32_t* a, const uint32_t* b) {
    asm volatile(
        "mma.sync.aligned.m16n8k16.row.col.f32.f16.f16.f32 "
        "{%0,%1,%2,%3}, {%4,%5,%6,%7}, {%8,%9}, {%0,%1,%2,%3};"
        : "+f"(c[0]), "+f"(c[1]), "+f"(c[2]), "+f"(c[3])
        : "r"(a[0]), "r"(a[1]), "r"(a[2]), "r"(a[3]), "r"(b[0]), "r"(b[1]));
}

// ---------------- f32 -> f16 convert pass ----------------
__global__ void f32_to_f16(const float* __restrict__ in, __half* __restrict__ out, long n4)
{
    long i = (long)blockIdx.x * blockDim.x + threadIdx.x;
    if (i >= n4) return;
    float4 v = ((const float4*)in)[i];
    __half2* o = (__half2*)out + 2 * i;
    o[0] = __floats2half2_rn(v.x, v.y);
    o[1] = __floats2half2_rn(v.z, v.w);
}

// ================= large tensor-core GEMM, fp16 in / fp32 accum, f32-or-f16 out =================
constexpr int HPAD = 72;
constexpr int HSTG = 128 * HPAD;
constexpr int NSTAGE = 3;
constexpr int GEMM_SMEM_H = NSTAGE * 2 * HSTG * 2; // 110,592 bytes

template<bool OUTH>
__global__ __launch_bounds__(256, 2)
void gemm_mma_h(const __half* __restrict__ A, const __half* __restrict__ Bw,
                void* __restrict__ Cv,
                int K, int lda, int ldb, int ldc, const float* __restrict__ bias)
{
    extern __shared__ __half hsm[];
    const int tid = threadIdx.x;
    const int wid = tid >> 5, lane = tid & 31;
    const int wm = wid >> 2, wn = wid & 3;
    const long m0 = (long)blockIdx.y * 128;
    const long n0 = (long)blockIdx.x * 128;

    const uint32_t sbase = smem_u32(hsm);
    const int g = lane >> 2, t4 = lane & 3;

    const int aRow = lane & 15, aCol = (lane >> 4) << 3;
    const int quad = lane >> 3, l8 = lane & 7;
    const int bRow = ((quad >> 1) << 3) + l8, bCol = (quad & 1) << 3;
    const uint32_t aFbase = sbase + (uint32_t)(((wm * 64 + aRow) * HPAD + aCol) * 2);
    const uint32_t bFbase = sbase + (uint32_t)((HSTG + (wn * 32 + bRow) * HPAD + bCol) * 2);

    float acc[4][4][4];
#pragma unroll
    for (int i = 0; i < 4; i++)
#pragma unroll
        for (int j = 0; j < 4; j++)
#pragma unroll
            for (int l = 0; l < 4; l++) acc[i][j][l] = 0.f;

    const int nch = K / 64;

    auto issue = [&](int s, int c) {
        const uint32_t so = (uint32_t)(s * 2 * HSTG * 2);
        const long ko = (long)c * 64;
#pragma unroll
        for (int i = 0; i < 4; i++) {
            const int idx = tid + i * 256;
            const int row = idx >> 3;
            const int sg = (idx & 7) << 3;
            const uint32_t soff = so + (uint32_t)((row * HPAD + sg) * 2);
            cpa16(sbase + soff, A + (m0 + row) * (long)lda + ko + sg);
            cpa16(sbase + (uint32_t)(HSTG * 2) + soff, Bw + (n0 + row) * (long)ldb + ko + sg);
        }
        CP_COMMIT();
    };

    issue(0, 0);
    if (nch > 1) issue(1, 1); else CP_COMMIT();

    for (int c = 0; c < nch; c++) {
        cp_wait<1>();
        __syncthreads();
        if (c + 2 < nch) issue((c + 2) % NSTAGE, c + 2);
        else CP_COMMIT();

        const int s = c % NSTAGE;
        const uint32_t so = (uint32_t)(s * 2 * HSTG * 2);
#pragma unroll
        for (int ks = 0; ks < 4; ks++) {
            uint32_t a[4][4], b[4][2];
#pragma unroll
            for (int mt = 0; mt < 4; mt++)
                ldsm_x4(a[mt][0], a[mt][1], a[mt][2], a[mt][3],
                        aFbase + so + (uint32_t)(((mt * 16) * HPAD + ks * 16) * 2));
#pragma unroll
            for (int j = 0; j < 2; j++)
                ldsm_x4(b[2 * j][0], b[2 * j][1], b[2 * j + 1][0], b[2 * j + 1][1],
                        bFbase + so + (uint32_t)(((j * 16) * HPAD + ks * 16) * 2));
#pragma unroll
            for (int mt = 0; mt < 4; mt++)
#pragma unroll
                for (int nt = 0; nt < 4; nt++)
                    mma_f16(acc[mt][nt], a[mt], b[nt]);
        }
    }

    const long rowBase = m0 + wm * 64 + g;
#pragma unroll
    for (int mt = 0; mt < 4; mt++) {
        const long r0 = rowBase + mt * 16;
#pragma unroll
        for (int nt = 0; nt < 4; nt++) {
            const long col = n0 + wn * 32 + nt * 8 + t4 * 2;
            float2 v0 = make_float2(acc[mt][nt][0], acc[mt][nt][1]);
            float2 v1 = make_float2(acc[mt][nt][2], acc[mt][nt][3]);
            if (bias) {
                float2 bb = *(const float2*)&bias[col];
                v0.x += bb.x; v0.y += bb.y;
                v1.x += bb.x; v1.y += bb.y;
            }
            if (OUTH) {
                __half* C = (__half*)Cv;
                *(__half2*)&C[r0 * (long)ldc + col] = __floats2half2_rn(v0.x, v0.y);
                *(__half2*)&C[(r0 + 8) * (long)ldc + col] = __floats2half2_rn(v1.x, v1.y);
            } else {
                float* C = (float*)Cv;
                *(float2*)&C[r0 * (long)ldc + col] = v0;
                *(float2*)&C[(r0 + 8) * (long)ldc + col] = v1;
            }
        }
    }
}

// ================= fused stage-1 (flash): all-f16 MMA =================
// smem (halfs): AgS[144][72], Kt[64][72], Vs[64][72], Ps[144][72]
constexpr int S1_AGP = 72, S1_KP = 72, S1_VP = 72, S1_PP = 72;
constexpr int S1_KT_OFF = 144 * S1_AGP;
constexpr int S1_VS_OFF = S1_KT_OFF + 64 * S1_KP;
constexpr int S1_PS_OFF = S1_VS_OFF + 64 * S1_VP;
constexpr int S1_SMEM = (S1_PS_OFF + 144 * S1_PP) * 2;    // 59,904 bytes

__global__ __launch_bounds__(288)
void stage1_fused(const __half* __restrict__ qkv, const __half* __restrict__ agent,
                  float* __restrict__ part, float scale)
{
    extern __shared__ __half s1h[];
    __half* AgS = s1h;
    __half* Kt  = s1h + S1_KT_OFF;
    __half* Vs  = s1h + S1_VS_OFF;
    __half* Ps  = s1h + S1_PS_OFF;
    const uint32_t vsBase = smem_u32(Vs);

    const int z = blockIdx.y, split = blockIdx.x;
    const int b = z >> 3, h = z & 7;
    const int tid = threadIdx.x, wid = tid >> 5, lane = tid & 31;
    const int g = lane >> 2, t4 = lane & 3;
    const int quad = lane >> 3, l8 = lane & 7;

    const __half* Agz = agent + (long)b * AG * C_ + h * 64;
    const __half* Kz  = qkv + (long)b * N_ * 1536 + 512 + h * 64;
    const __half* Vz  = qkv + (long)b * N_ * 1536 + 1024 + h * 64;

    for (int i = tid; i < 144 * 8; i += 288) {
        int row = i >> 3, seg = (i & 7) << 3;
        *(uint4*)&AgS[row * S1_AGP + seg] = *(const uint4*)(Agz + (long)row * C_ + seg);
    }
    __syncthreads();

    const int r = wid * 16 + g;

    uint32_t afr[4][4];
#pragma unroll
    for (int ks = 0; ks < 4; ks++) {
        const __half* p = &AgS[r * S1_AGP + ks * 16 + 2 * t4];
        afr[ks][0] = *(const uint32_t*)(p);
        afr[ks][1] = *(const uint32_t*)(p + 8 * S1_AGP);
        afr[ks][2] = *(const uint32_t*)(p + 8);
        afr[ks][3] = *(const uint32_t*)(p + 8 * S1_AGP + 8);
    }

    float m0r = -3.4e38f, m1r = -3.4e38f, s0 = 0.f, s1 = 0.f;
    float O[8][4];
#pragma unroll
    for (int nt = 0; nt < 8; nt++)
#pragma unroll
        for (int l = 0; l < 4; l++) O[nt][l] = 0.f;

    int k0 = split * 448;
    for (int t = 0; t < 7; t++, k0 += 64) {
        __syncthreads();
        // raw half copies of K and V tiles [64 x 64]
        for (int i = tid; i < 64 * 8; i += 288) {
            int row = i >> 3, seg = (i & 7) << 3;
            *(uint4*)&Kt[row * S1_KP + seg] = *(const uint4*)(Kz + (long)(k0 + row) * 1536 + seg);
            *(uint4*)&Vs[row * S1_VP + seg] = *(const uint4*)(Vz + (long)(k0 + row) * 1536 + seg);
        }
        __syncthreads();

        // logits L[16 x 64] per warp, f16
        float L[8][4];
#pragma unroll
        for (int nt = 0; nt < 8; nt++)
#pragma unroll
            for (int l = 0; l < 4; l++) L[nt][l] = 0.f;
#pragma unroll
        for (int ks = 0; ks < 4; ks++) {
#pragma unroll
            for (int nt = 0; nt < 8; nt++) {
                uint32_t bb[2];
                const __half* p = &Kt[(nt * 8 + g) * S1_KP + ks * 16 + 2 * t4];
                bb[0] = *(const uint32_t*)(p);
                bb[1] = *(const uint32_t*)(p + 8);
                mma_f16(L[nt], afr[ks], bb);
            }
        }

        // online softmax
        float lm0 = -3.4e38f, lm1 = -3.4e38f;
#pragma unroll
        for (int nt = 0; nt < 8; nt++) {
            lm0 = fmaxf(lm0, fmaxf(L[nt][0], L[nt][1]));
            lm1 = fmaxf(lm1, fmaxf(L[nt][2], L[nt][3]));
        }
        lm0 *= scale; lm1 *= scale;
#pragma unroll
        for (int o = 1; o < 4; o <<= 1) {
            lm0 = fmaxf(lm0, __shfl_xor_sync(0xffffffffu, lm0, o));
            lm1 = fmaxf(lm1, __shfl_xor_sync(0xffffffffu, lm1, o));
        }
        float nm0 = fmaxf(m0r, lm0), nm1 = fmaxf(m1r, lm1);
        float al0 = __expf(m0r - nm0), al1 = __expf(m1r - nm1);
        s0 *= al0; s1 *= al1;
#pragma unroll
        for (int nt = 0; nt < 8; nt++) {
            O[nt][0] *= al0; O[nt][1] *= al0; O[nt][2] *= al1; O[nt][3] *= al1;
            float p0 = __expf(L[nt][0] * scale - nm0); s0 += p0;
            float p1 = __expf(L[nt][1] * scale - nm0); s0 += p1;
            float p2 = __expf(L[nt][2] * scale - nm1); s1 += p2;
            float p3 = __expf(L[nt][3] * scale - nm1); s1 += p3;
            int col = nt * 8 + 2 * t4;
            *(__half2*)&Ps[r * S1_PP + col]       = __floats2half2_rn(p0, p1);
            *(__half2*)&Ps[(r + 8) * S1_PP + col] = __floats2half2_rn(p2, p3);
        }
        m0r = nm0; m1r = nm1;

        // O += P(16x64) @ V(64x64)  (f16; B-frag = V^T via ldmatrix.trans)
#pragma unroll
        for (int ks = 0; ks < 4; ks++) {
            uint32_t a2[4];
            const __half* p = &Ps[r * S1_PP + ks * 16 + 2 * t4];
            a2[0] = *(const uint32_t*)(p);
            a2[1] = *(const uint32_t*)(p + 8 * S1_PP);
            a2[2] = *(const uint32_t*)(p + 8);
            a2[3] = *(const uint32_t*)(p + 8 * S1_PP + 8);
            uint32_t bfr[8][2];
#pragma unroll
            for (int pr = 0; pr < 4; pr++) {
                uint32_t addr = vsBase + (uint32_t)(((ks * 16 + ((quad & 1) << 3) + l8) * S1_VP
                                + pr * 16 + ((quad >> 1) << 3)) * 2);
                ldsm_x4_t(bfr[2 * pr][0], bfr[2 * pr][1], bfr[2 * pr + 1][0], bfr[2 * pr + 1][1], addr);
            }
#pragma unroll
            for (int nt = 0; nt < 8; nt++)
                mma_f16(O[nt], a2, bfr[nt]);
        }
    }

#pragma unroll
    for (int o = 1; o < 4; o <<= 1) {
        s0 += __shfl_xor_sync(0xffffffffu, s0, o);
        s1 += __shfl_xor_sync(0xffffffffu, s1, o);
    }

    const long pb = ((long)z * 7 + split) * 144;
#pragma unroll
    for (int nt = 0; nt < 8; nt++) {
        int col = nt * 8 + 2 * t4;
        *(float2*)&part[(pb + r) * 64 + col]     = make_float2(O[nt][0], O[nt][1]);
        *(float2*)&part[(pb + r + 8) * 64 + col] = make_float2(O[nt][2], O[nt][3]);
    }
    if (t4 == 0) {
        part[PART_M + pb + r]     = m0r;  part[PART_S + pb + r]     = s0;
        part[PART_M + pb + r + 8] = m1r;  part[PART_S + pb + r + 8] = s1;
    }
}

// merge 7 split partials -> agent_v (half)
__global__ void stage1_merge(const float* __restrict__ part, __half* __restrict__ av)
{
    long i = (long)blockIdx.x * 256 + threadIdx.x;
    if (i >= (long)128 * 144 * 16) return;
    int d4 = (int)(i & 15);
    long t = i >> 4;
    int p = (int)(t % 144);
    int z = (int)(t / 144);
    long base = (long)z * 7 * 144 + p;

    float M = -3.4e38f;
#pragma unroll
    for (int sp = 0; sp < 7; sp++)
        M = fmaxf(M, part[PART_M + base + sp * 144]);
    float den = 0.f;
    float4 acc = make_float4(0.f, 0.f, 0.f, 0.f);
#pragma unroll
    for (int sp = 0; sp < 7; sp++) {
        float w = __expf(part[PART_M + base + sp * 144] - M);
        den += w * part[PART_S + base + sp * 144];
        float4 o = *(const float4*)&part[(base + sp * 144) * 64 + d4 * 4];
        acc.x += w * o.x; acc.y += w * o.y; acc.z += w * o.z; acc.w += w * o.w;
    }
    float inv = 1.f / den;
    __half2 h0 = __floats2half2_rn(acc.x * inv, acc.y * inv);
    __half2 h1 = __floats2half2_rn(acc.z * inv, acc.w * inv);
    uint2 pk = make_uint2(*(uint32_t*)&h0, *(uint32_t*)&h1);
    *(uint2*)&av[((long)z * 144 + p) * 64 + d4 * 4] = pk;
}

// ================= fused stage-2: all-f16 MMA + depthwise conv =================
// smem: As h[128][72] + Bs h[144][72] (alias Ps h[128][152]); Vs h[144][72]; Ws/Bb f32
constexpr int S2_AP = 72, S2_BP = 72, S2_PP = 152, S2_VP = 72;
constexpr int S2_ALIAS_H = (128 + 144) * 72;              // 19,584 halfs (>= 128*152)
constexpr int S2_VS_B = S2_ALIAS_H * 2;                   // 39,168
constexpr int S2_W_B  = S2_VS_B + 144 * S2_VP * 2;        // 59,904
constexpr int S2_SMEM = S2_W_B + (576 + 64) * 4;          // 62,464 bytes

__global__ __launch_bounds__(256)
void stage2_fused(const __half* __restrict__ Q, const __half* __restrict__ Ag,
                  const __half* __restrict__ Av, __half* __restrict__ Y,
                  const float* __restrict__ dwcW, const float* __restrict__ dwcB,
                  float scale)
{
    extern __shared__ char s2sm[];
    __half* As = (__half*)s2sm;
    __half* Bs = (__half*)s2sm + 128 * S2_AP;
    __half* Ps = (__half*)s2sm;
    __half* Vs = (__half*)(s2sm + S2_VS_B);
    float*  Ws = (float*)(s2sm + S2_W_B);
    float*  Bb = Ws + 576;
    const uint32_t vsBase = smem_u32(Vs);

    const int z = blockIdx.y;
    const int b = z >> 3, h = z & 7;
    const __half* Qz  = Q + (long)b * N_ * 1536 + h * 64;
    const __half* Agz = Ag + (long)b * AG * C_ + h * 64;
    const __half* Avz = Av + (long)z * AG * 64;
    const __half* vb  = Q + (long)b * N_ * 1536 + 1024 + h * 64;
    __half* Yz = Y + (long)b * N_ * C_ + h * 64;

    const int tid = threadIdx.x;
    const int wid = tid >> 5, lane = tid & 31;
    const int g = lane >> 2, t4 = lane & 3;
    const int quad = lane >> 3, l8 = lane & 7;
    const int m0 = blockIdx.x * 128;

#pragma unroll
    for (int i = 0; i < 4; i++) {
        int idx = tid + i * 256;
        int row = idx >> 3, seg = (idx & 7) << 3;
        uint4 v = make_uint4(0u, 0u, 0u, 0u);
        if (m0 + row < N_)
            v = *(const uint4*)(Qz + (long)(m0 + row) * 1536 + seg);
        *(uint4*)&As[row * S2_AP + seg] = v;
    }
    for (int i = tid; i < 144 * 8; i += 256) {
        int row = i >> 3, seg = (i & 7) << 3;
        *(uint4*)&Bs[row * S2_BP + seg] = *(const uint4*)(Agz + (long)row * C_ + seg);
        *(uint4*)&Vs[row * S2_VP + seg] = *(const uint4*)(Avz + (long)row * 64 + seg);
    }
    for (int i = tid; i < 640; i += 256) {
        if (i < 576) Ws[i] = dwcW[h * 576 + i];
        else         Bb[i - 576] = dwcB[h * 64 + i - 576];
    }
    __syncthreads();

    // logits L[128 x 144], f16
    const int r = wid * 16 + g;
    float accL[18][4];
#pragma unroll
    for (int nt = 0; nt < 18; nt++)
#pragma unroll
        for (int l = 0; l < 4; l++) accL[nt][l] = 0.f;

#pragma unroll
    for (int ks = 0; ks < 4; ks++) {
        uint32_t a[4];
        {
            const __half* p = &As[r * S2_AP + ks * 16 + 2 * t4];
            a[0] = *(const uint32_t*)(p);
            a[1] = *(const uint32_t*)(p + 8 * S2_AP);
            a[2] = *(const uint32_t*)(p + 8);
            a[3] = *(const uint32_t*)(p + 8 * S2_AP + 8);
        }
#pragma unroll
        for (int nt = 0; nt < 18; nt++) {
            uint32_t bfr[2];
            const __half* p = &Bs[(nt * 8 + g) * S2_BP + ks * 16 + 2 * t4];
            bfr[0] = *(const uint32_t*)(p);
            bfr[1] = *(const uint32_t*)(p + 8);
            mma_f16(accL[nt], a, bfr);
        }
    }

    // softmax over 144
    float m0r = -3.4e38f, m1r = -3.4e38f;
#pragma unroll
    for (int nt = 0; nt < 18; nt++) {
        m0r = fmaxf(m0r, fmaxf(accL[nt][0], accL[nt][1]));
        m1r = fmaxf(m1r, fmaxf(accL[nt][2], accL[nt][3]));
    }
    m0r *= scale; m1r *= scale;
#pragma unroll
    for (int o = 1; o < 4; o <<= 1) {
        m0r = fmaxf(m0r, __shfl_xor_sync(0xffffffffu, m0r, o));
        m1r = fmaxf(m1r, __shfl_xor_sync(0xffffffffu, m1r, o));
    }
    float s0 = 0.f, s1 = 0.f;
#pragma unroll
    for (int nt = 0; nt < 18; nt++) {
        accL[nt][0] = __expf(accL[nt][0] * scale - m0r); s0 += accL[nt][0];
        accL[nt][1] = __expf(accL[nt][1] * scale - m0r); s0 += accL[nt][1];
        accL[nt][2] = __expf(accL[nt][2] * scale - m1r); s1 += accL[nt][2];
        accL[nt][3] = __expf(accL[nt][3] * scale - m1r); s1 += accL[nt][3];
    }
#pragma unroll
    for (int o = 1; o < 4; o <<= 1) {
        s0 += __shfl_xor_sync(0xffffffffu, s0, o);
        s1 += __shfl_xor_sync(0xffffffffu, s1, o);
    }
    const float inv0 = 1.0f / s0, inv1 = 1.0f / s1;

    __syncthreads();   // As/Bs reads done before Ps overwrite

#pragma unroll
    for (int nt = 0; nt < 18; nt++) {
        const int col = nt * 8 + 2 * t4;
        *(__half2*)&Ps[r * S2_PP + col]       = __floats2half2_rn(accL[nt][0] * inv0, accL[nt][1] * inv0);
        *(__half2*)&Ps[(r + 8) * S2_PP + col] = __floats2half2_rn(accL[nt][2] * inv1, accL[nt][3] * inv1);
    }
    __syncthreads();

    // out = P @ agent_v  (f16; B-frag = Av^T via ldmatrix.trans; K=144 = 9 k16 steps)
    float acc2[8][4];
#pragma unroll
    for (int nt = 0; nt < 8; nt++)
#pragma unroll
        for (int l = 0; l < 4; l++) acc2[nt][l] = 0.f;

#pragma unroll
    for (int ks = 0; ks < 9; ks++) {
        uint32_t a[4];
        {
            const __half* p = &Ps[r * S2_PP + ks * 16 + 2 * t4];
            a[0] = *(const uint32_t*)(p);
            a[1] = *(const uint32_t*)(p + 8 * S2_PP);
            a[2] = *(const uint32_t*)(p + 8);
            a[3] = *(const uint32_t*)(p + 8 * S2_PP + 8);
        }
        uint32_t bfr[8][2];
#pragma unroll
        for (int pr = 0; pr < 4; pr++) {
            uint32_t addr = vsBase + (uint32_t)(((ks * 16 + ((quad & 1) << 3) + l8) * S2_VP
                            + pr * 16 + ((quad >> 1) << 3)) * 2);
            ldsm_x4_t(bfr[2 * pr][0], bfr[2 * pr][1], bfr[2 * pr + 1][0], bfr[2 * pr + 1][1], addr);
        }
#pragma unroll
        for (int nt = 0; nt < 8; nt++)
            mma_f16(acc2[nt], a, bfr[nt]);
    }

    // epilogue: + depthwise 3x3 conv + bias, write half
    const int gr = m0 + r;
#pragma unroll
    for (int rr = 0; rr < 2; rr++) {
        const int l = gr + rr * 8;
        if (l >= N_) continue;
        const int hh = l / 56, ww = l - hh * 56;
        float add[16];
#pragma unroll
        for (int nt = 0; nt < 8; nt++) {
            int c0 = nt * 8 + 2 * t4;
            add[nt * 2]     = Bb[c0];
            add[nt * 2 + 1] = Bb[c0 + 1];
        }
#pragma unroll
        for (int kh = 0; kh < 3; kh++) {
            int h2 = hh + kh - 1;
            if (h2 < 0 || h2 >= 56) continue;
#pragma unroll
            for (int kw = 0; kw < 3; kw++) {
                int w2 = ww + kw - 1;
                if (w2 < 0 || w2 >= 56) continue;
                const __half* vrow = vb + (long)(h2 * 56 + w2) * 1536;
                const int j = kh * 3 + kw;
#pragma unroll
                for (int nt = 0; nt < 8; nt++) {
                    int c0 = nt * 8 + 2 * t4;
                    float2 vv = __half22float2(*(const __half2*)&vrow[c0]);
                    add[nt * 2]     = fmaf(vv.x, Ws[c0 * 9 + j],       add[nt * 2]);
                    add[nt * 2 + 1] = fmaf(vv.y, Ws[(c0 + 1) * 9 + j], add[nt * 2 + 1]);
                }
            }
        }
#pragma unroll
        for (int nt = 0; nt < 8; nt++) {
            const int col = nt * 8 + 2 * t4;
            __half2 hv = __floats2half2_rn(acc2[nt][rr * 2]     + add[nt * 2],
                                           acc2[nt][rr * 2 + 1] + add[nt * 2 + 1]);
            *(__half2*)&Yz[(long)l * C_ + col] = hv;
        }
    }
}

// ---------------- adaptive avg pool of q (half) -> agent tokens (half) ----------------
__global__ void pool_kernel(const __half* __restrict__ qkv, __half* __restrict__ agent)
{
    int b = blockIdx.x;
    int pq = blockIdx.y;
    int p = pq / POOL, q = pq % POOL;
    int ch = threadIdx.x;
    int hs = (p * HH) / POOL, he = ((p + 1) * HH + POOL - 1) / POOL;
    int ws = (q * HH) / POOL, we = ((q + 1) * HH + POOL - 1) / POOL;
    float inv = 1.0f / (float)((he - hs) * (we - ws));
    const __half* base = qkv + (long)b * N_ * 1536;
    float s = 0.f;
    for (int h = hs; h < he; h++)
        for (int w = ws; w < we; w++)
            s += __half2float(base[(long)(h * HH + w) * 1536 + ch]);
    agent[((long)b * AG + pq) * C_ + ch] = __float2half(s * inv);
}

// ---------------- launch ----------------
extern "C" void kernel_launch(void* const* d_in, const int* in_sizes, int n_in,
                              void* d_out, int out_size)
{
    const float* x      = (const float*)d_in[0];
    const float* qkv_w  = (const float*)d_in[1];
    const float* proj_w = (const float*)d_in[2];
    const float* proj_b = (const float*)d_in[3];
    const float* dwc_w  = (const float*)d_in[4];
    const float* dwc_b  = (const float*)d_in[5];
    float* out = (float*)d_out;

    __half *qkvh, *agenth, *wh, *avh;
    float *S;
    cudaGetSymbolAddress((void**)&qkvh,   g_qkvh);
    cudaGetSymbolAddress((void**)&agenth, g_agenth);
    cudaGetSymbolAddress((void**)&S,      g_S);
    cudaGetSymbolAddress((void**)&avh,    g_avh);
    cudaGetSymbolAddress((void**)&wh,     g_wh);
    __half* xh = (__half*)S;
    __half* yh = (__half*)S;

    cudaFuncSetAttribute(gemm_mma_h<true>,  cudaFuncAttributeMaxDynamicSharedMemorySize, GEMM_SMEM_H);
    cudaFuncSetAttribute(gemm_mma_h<false>, cudaFuncAttributeMaxDynamicSharedMemorySize, GEMM_SMEM_H);
    cudaFuncSetAttribute(stage1_fused, cudaFuncAttributeMaxDynamicSharedMemorySize, S1_SMEM);
    cudaFuncSetAttribute(stage2_fused, cudaFuncAttributeMaxDynamicSharedMemorySize, S2_SMEM);

    const float scale = 0.125f;

    // 0) convert x, qkv_w, proj_w to fp16 (proj_w stored at wh+786432)
    {
        long n4 = Y_ELEMS / 4;
        f32_to_f16<<<(int)((n4 + 255) / 256), 256>>>(x, xh, n4);
        long w4 = 786432 / 4;
        f32_to_f16<<<(int)((w4 + 255) / 256), 256>>>(qkv_w, wh, w4);
        long p4 = 262144 / 4;
        f32_to_f16<<<(int)((p4 + 255) / 256), 256>>>(proj_w, wh + 786432, p4);
    }

    // 1) qkv(half) = x @ qkv_w^T
    gemm_mma_h<true><<<dim3(12, 392), 256, GEMM_SMEM_H>>>(xh, wh, qkvh, 512, 512, 512, 1536, nullptr);

    // 2) agent tokens (half)
    pool_kernel<<<dim3(B_, AG), 512>>>(qkvh, agenth);

    // 3+4+5) fused flash stage-1 -> partials (g_S; xh dead) -> merge into agent_v (half)
    stage1_fused<<<dim3(7, 128), 288, S1_SMEM>>>(qkvh, agenth, S, scale);
    stage1_merge<<<1152, 256>>>(S, avh);

    // 6+7+8+9) fused: y(half) = softmax(scale*qh@agent^T) @ agent_v + dwc(v) + dwc_b
    stage2_fused<<<dim3(25, 128), 256, S2_SMEM>>>(qkvh, agenth, avh, yh, dwc_w, dwc_b, scale);

    // 10) out = y @ proj_w^T + proj_b
    gemm_mma_h<false><<<dim3(4, 392), 256, GEMM_SMEM_H>>>(yh, wh + 786432, out, 512, 512, 512, 512, proj_b);
}